// round 15
// baseline (speedup 1.0000x reference)
#include <cuda_runtime.h>
#include <cuda_fp16.h>
#include <math.h>
#include <stdint.h>

#define BZ   128
#define T    32
#define D    768
#define DFF  3072
#define NE   8
#define NROWS 256
#define OUT_ELEMS (NROWS*T*D)
#define MAX_TILES 72

#define NT        256                 // CTA N tile
#define KC        64                  // K chunk
#define STAGES    4
#define AS_H      72                  // A smem row stride (halves), LDSM-clean
#define BS_H      264                 // B smem k-row stride (halves), LDSM-clean
#define A_STAGE_H (128*AS_H)          // 9216 halves
#define B_STAGE_H (KC*BS_H)           // 16896 halves
#define STAGE_H   (A_STAGE_H + B_STAGE_H)      // 26112 halves
#define SSZ       (STAGE_H*2)                  // stage bytes (52224)
#define SMEM_BYTES (STAGES*SSZ)                // 208896 B

// ---------------- scratch ---------------------------------------------------
__device__ int   g_sel[NROWS];
__device__ int   g_perm[NROWS];
__device__ int   g_tile_e[MAX_TILES];
__device__ int   g_tile_p0[MAX_TILES];
__device__ int   g_tile_rows[MAX_TILES];
__device__ int   g_ntiles;
__device__ __half g_xh[(size_t)BZ*T*D];        // fp16 copy of x
__device__ __half g_h[(size_t)NROWS*T*DFF];    // fp16 intermediate, grouped
__device__ __half g_w1h[(size_t)NE*D*DFF];     // fp16 W1
__device__ __half g_w2h[(size_t)NE*DFF*D];     // fp16 W2

__device__ __forceinline__ float gelu_exact(float v) {
    return 0.5f * v * (1.0f + erff(v * 0.70710678118654752f));
}
__device__ __forceinline__ uint32_t pack_h2(float lo, float hi) {
    uint32_t d;
    asm("cvt.rn.f16x2.f32 %0, %1, %2;" : "=r"(d) : "f"(hi), "f"(lo));
    return d;
}
__device__ __forceinline__ void mma_f16(float* c,
                                        uint32_t a0, uint32_t a1, uint32_t a2, uint32_t a3,
                                        uint32_t b0, uint32_t b1) {
    asm volatile(
        "mma.sync.aligned.m16n8k16.row.col.f32.f16.f16.f32 "
        "{%0,%1,%2,%3}, {%4,%5,%6,%7}, {%8,%9}, {%0,%1,%2,%3};"
        : "+f"(c[0]), "+f"(c[1]), "+f"(c[2]), "+f"(c[3])
        : "r"(a0), "r"(a1), "r"(a2), "r"(a3), "r"(b0), "r"(b1));
}
__device__ __forceinline__ void ldsm4(uint32_t* r, uint32_t addr) {
    asm volatile("ldmatrix.sync.aligned.m8n8.x4.shared.b16 {%0,%1,%2,%3}, [%4];"
        : "=r"(r[0]), "=r"(r[1]), "=r"(r[2]), "=r"(r[3]) : "r"(addr));
}
__device__ __forceinline__ void ldsm4t(uint32_t* r, uint32_t addr) {
    asm volatile("ldmatrix.sync.aligned.m8n8.x4.trans.shared.b16 {%0,%1,%2,%3}, [%4];"
        : "=r"(r[0]), "=r"(r[1]), "=r"(r[2]), "=r"(r[3]) : "r"(addr));
}
__device__ __forceinline__ void cp16(uint32_t saddr, const void* g) {
    asm volatile("cp.async.cg.shared.global [%0], [%1], 16;" :: "r"(saddr), "l"(g));
}

// ---------------- kernel 0a: x -> fp16 --------------------------------------
__global__ void half_x_kernel(const float* __restrict__ x) {
    int i = blockIdx.x * blockDim.x + threadIdx.x;
    const int n4 = BZ*T*D/4;
    if (i < n4) {
        float4 v = ((const float4*)x)[i];
        ((uint2*)g_xh)[i] = make_uint2(pack_h2(v.x, v.y), pack_h2(v.z, v.w));
    }
}

// ---------------- kernel 0b/0c: W1 / W2 -> fp16 ------------------------------
__global__ void wcvt1_kernel(const float* __restrict__ W1) {
    size_t i = (size_t)blockIdx.x * blockDim.x + threadIdx.x;
    const size_t n4 = (size_t)NE*D*DFF/4;
    if (i < n4) {
        float4 a = ((const float4*)W1)[i];
        ((uint2*)g_w1h)[i] = make_uint2(pack_h2(a.x, a.y), pack_h2(a.z, a.w));
    }
}
__global__ void wcvt2_kernel(const float* __restrict__ W2) {
    size_t i = (size_t)blockIdx.x * blockDim.x + threadIdx.x;
    const size_t n4 = (size_t)NE*DFF*D/4;
    if (i < n4) {
        float4 b = ((const float4*)W2)[i];
        ((uint2*)g_w2h)[i] = make_uint2(pack_h2(b.x, b.y), pack_h2(b.z, b.w));
    }
}

// ---------------- kernel 1: fused avg + router ------------------------------
__global__ void avg_router_kernel(const float* __restrict__ x,
                                  const float* __restrict__ Wg,
                                  float* __restrict__ dout, int out_size) {
    __shared__ float xa[D];
    int b = blockIdx.x;
    for (int d = threadIdx.x; d < D; d += blockDim.x) {
        float s = 0.f;
        #pragma unroll
        for (int t = 0; t < T; t++) s += x[((size_t)b*T + t)*D + d];
        xa[d] = s * (1.0f / T);
    }
    __syncthreads();
    if (threadIdx.x < 32) {
        int lane = threadIdx.x;
        int e = lane & 7;
        int chunk = lane >> 3;
        float part = 0.f;
        for (int d = chunk*192; d < (chunk+1)*192; d++) part += xa[d] * Wg[d*NE + e];
        part += __shfl_down_sync(0xffffffffu, part, 16);
        part += __shfl_down_sync(0xffffffffu, part, 8);
        float lv[NE];
        #pragma unroll
        for (int i = 0; i < NE; i++) lv[i] = __shfl_sync(0xffffffffu, part, i);
        if (lane == 0) {
            float mx = lv[0];
            #pragma unroll
            for (int i = 1; i < NE; i++) mx = fmaxf(mx, lv[i]);
            float p[NE]; float sum = 0.f;
            #pragma unroll
            for (int i = 0; i < NE; i++) { p[i] = __expf(lv[i] - mx); sum += p[i]; }
            float inv = 1.0f / sum;
            #pragma unroll
            for (int i = 0; i < NE; i++) p[i] *= inv;
            int i0 = 0;
            #pragma unroll
            for (int i = 1; i < NE; i++) if (p[i] > p[i0]) i0 = i;
            int i1 = (i0 == 0) ? 1 : 0;
            #pragma unroll
            for (int i = 0; i < NE; i++) if (i != i0 && p[i] > p[i1]) i1 = i;
            g_sel[2*b] = i0; g_sel[2*b+1] = i1;
            if (out_size >= OUT_ELEMS + 2*NROWS) {
                dout[OUT_ELEMS + 2*b]             = p[i0];
                dout[OUT_ELEMS + 2*b + 1]         = p[i1];
                dout[OUT_ELEMS + NROWS + 2*b]     = (float)i0;
                dout[OUT_ELEMS + NROWS + 2*b + 1] = (float)i1;
            }
        }
    }
}

// ---------------- kernel 2: group rows by expert ----------------------------
__global__ void group_kernel() {
    __shared__ int ssel[NROWS];
    __shared__ int shist[NE];
    __shared__ int soff[NE];
    int t = threadIdx.x;
    if (t < NE) shist[t] = 0;
    __syncthreads();
    ssel[t] = g_sel[t];
    __syncthreads();
    atomicAdd(&shist[ssel[t]], 1);
    __syncthreads();
    if (t == 0) {
        int pos = 0, tiles = 0;
        for (int e = 0; e < NE; e++) {
            soff[e] = pos;
            int cnt = shist[e];
            for (int r = 0; r < cnt; r += 4) {
                g_tile_e[tiles] = e; g_tile_p0[tiles] = pos + r;
                g_tile_rows[tiles] = min(4, cnt - r); tiles++;
            }
            pos += cnt;
        }
        g_ntiles = tiles;
    }
    __syncthreads();
    int mysel = ssel[t], rank = 0;
    for (int m = 0; m < NROWS; m++)
        if (m < t && ssel[m] == mysel) rank++;
    g_perm[soff[mysel] + rank] = t;
}

// ---------------- fp16 m16n8k16 GEMM, 4-stage, single consume body ----------
// PHASE 1 (part = y-half): g_h[:, part*1536 + y*256 ...] = fp16(gelu(...))
// PHASE 2 (part = kp):     out[perm] += g_h @ W2h[e](+b2 on kp0)
// CTA 128x256, 512 threads / 16 warps (2m x 8n), warp tile 64x32.
template<int PHASE>
__global__ __launch_bounds__(512, 1) void ffn_mma(
    const float* __restrict__ b1f, const float* __restrict__ b2f,
    float* __restrict__ out, int part)
{
    const int mt = blockIdx.x;
    if (mt >= g_ntiles) return;
    const int e     = g_tile_e[mt];
    const int p0    = g_tile_p0[mt];
    const int nrows = g_tile_rows[mt];
    const int kp    = (PHASE == 2) ? part : 0;
    const int NF    = (PHASE == 1) ? DFF : D;
    const int kbase = (PHASE == 2) ? kp * (DFF/2) : 0;
    const int NC    = ((PHASE == 1) ? D : DFF/2) / KC;
    const __half* __restrict__ Bsrc = (PHASE == 1) ? (g_w1h + (size_t)e*D*DFF)
                                                   : (g_w2h + (size_t)e*DFF*D);
    const int n0 = (PHASE == 1) ? (part*(DFF/2) + blockIdx.y * NT)
                                : blockIdx.y * NT;
    const int tid = threadIdx.x, wid = tid >> 5, lane = tid & 31;

    extern __shared__ __half smh[];
    uint32_t sbase = (uint32_t)__cvta_generic_to_shared(smh);

    // ---- A loader: 128 rows x 64 halves (8x16B segs), 4 thr/row x 2 segs ----
    const int arow = tid >> 2, aseg = (tid & 3) * 2;
    const __half* aglob;
    {
        int r = ((arow >> 5) < nrows) ? arow : (arow & 31);
        if (PHASE == 1) {
            int n = g_perm[p0 + (r >> 5)];
            aglob = g_xh + ((size_t)(n >> 1)*T + (r & 31)) * (size_t)D;
        } else {
            aglob = g_h + ((size_t)(p0*T + r)) * (size_t)DFF;
        }
    }
    // ---- B loader: 64 k-rows x 256 halves (32x16B segs), 8 thr/row x 4 segs
    const int brow = tid >> 3, bseg = tid & 7;
    const __half* bglob = Bsrc + (size_t)brow*NF + n0;

    const uint32_t aStsB = sbase + (arow*AS_H)*2;
    const uint32_t bStsB = sbase + (A_STAGE_H + brow*BS_H)*2;

    #define ISSUE(k0, soff) do {                                              \
        cp16(aStsB + (soff) + (aseg+0)*16, aglob + (k0) + (aseg+0)*8);        \
        cp16(aStsB + (soff) + (aseg+1)*16, aglob + (k0) + (aseg+1)*8);        \
        _Pragma("unroll")                                                     \
        for (int i = 0; i < 4; i++)                                           \
            cp16(bStsB + (soff) + (bseg + 8*i)*16,                            \
                 bglob + (size_t)(k0)*NF + (bseg + 8*i)*8);                   \
    } while (0)

    // ---- ldmatrix lane bases (stage 0) ----
    const int wm = (wid & 1) * 64;
    const int wn = (wid >> 1) * 32;
    const int lm = lane >> 3;
    const int lr = lane & 7;
    const uint32_t aLdB = sbase + ((wm + (lm & 1)*8 + lr)*AS_H + (lm >> 1)*8)*2;
    const uint32_t bLdB = sbase + (A_STAGE_H + ((lm & 1)*8 + lr)*BS_H
                                   + wn + (lm >> 1)*8)*2;

    float acc[4][4][4];
    #pragma unroll
    for (int i = 0; i < 4; i++)
        #pragma unroll
        for (int j = 0; j < 4; j++)
            #pragma unroll
            for (int q = 0; q < 4; q++) acc[i][j][q] = 0.f;

    // ---- prologue: chunks 0..2 in flight ----
    ISSUE(kbase + 0*KC, 0*SSZ);
    asm volatile("cp.async.commit_group;" ::: "memory");
    ISSUE(kbase + 1*KC, 1*SSZ);
    asm volatile("cp.async.commit_group;" ::: "memory");
    ISSUE(kbase + 2*KC, 2*SSZ);
    asm volatile("cp.async.commit_group;" ::: "memory");

    uint32_t consOff = 0, issOff = 3*SSZ;

    // ---- main loop: single consume body, running stage offsets ----
    for (int c = 0; c < NC; c++) {
        asm volatile("cp.async.wait_group 2;" ::: "memory");  // chunk c landed
        __syncthreads();          // visible to all; consume(c-1) done by all
        if (c + 3 < NC) ISSUE(kbase + (c + 3)*KC, issOff);
        asm volatile("cp.async.commit_group;" ::: "memory");

        const uint32_t aL = aLdB + consOff;
        const uint32_t bL = bLdB + consOff;
        #pragma unroll
        for (int ks = 0; ks < 4; ks++) {
            uint32_t af[4][4], bf[2][4];
            #pragma unroll
            for (int mi = 0; mi < 4; mi++)
                ldsm4(af[mi], aL + (mi*16*AS_H + ks*16)*2);
            #pragma unroll
            for (int nj = 0; nj < 2; nj++)
                ldsm4t(bf[nj], bL + (ks*16*BS_H + nj*16)*2);
            #pragma unroll
            for (int mi = 0; mi < 4; mi++) {
                #pragma unroll
                for (int nj = 0; nj < 2; nj++) {
                    mma_f16(acc[mi][2*nj],   af[mi][0], af[mi][1], af[mi][2],
                            af[mi][3], bf[nj][0], bf[nj][1]);
                    mma_f16(acc[mi][2*nj+1], af[mi][0], af[mi][1], af[mi][2],
                            af[mi][3], bf[nj][2], bf[nj][3]);
                }
            }
        }
        consOff = (consOff == 3*SSZ) ? 0 : consOff + SSZ;
        issOff  = (issOff  == 3*SSZ) ? 0 : issOff  + SSZ;
    }

    // ---- epilogue ----
    const int g = lane >> 2, t4 = lane & 3;
    const float* bias = (PHASE == 1) ? (b1f + e*DFF + n0) : (b2f + e*D + n0);
    #pragma unroll
    for (int mi = 0; mi < 4; mi++) {
        #pragma unroll
        for (int h = 0; h < 2; h++) {
            int r = wm + 16*mi + g + 8*h;
            int br = r >> 5;
            if (br >= nrows) continue;
            if (PHASE == 1) {
                __half* dst = g_h + ((size_t)(p0*T + r)) * (size_t)DFF + n0;
                #pragma unroll
                for (int ni = 0; ni < 4; ni++) {
                    int col = wn + 8*ni + 2*t4;
                    float v0 = gelu_exact(acc[mi][ni][2*h + 0] + bias[col]);
                    float v1 = gelu_exact(acc[mi][ni][2*h + 1] + bias[col + 1]);
                    *(uint32_t*)(dst + col) = pack_h2(v0, v1);
                }
            } else {
                int n = g_perm[p0 + br];
                float* dst = out + ((size_t)n*T + (r & 31)) * (size_t)D + n0;
                #pragma unroll
                for (int ni = 0; ni < 4; ni++) {
                    int col = wn + 8*ni + 2*t4;
                    float v0 = acc[mi][ni][2*h + 0];
                    float v1 = acc[mi][ni][2*h + 1];
                    if (kp == 0) { v0 += bias[col]; v1 += bias[col + 1]; }
                    atomicAdd(dst + col,     v0);   // 2 contributions onto 0:
                    atomicAdd(dst + col + 1, v1);   // order-invariant
                }
            }
        }
    }
    #undef ISSUE
}

// ---------------- launch: cross-stream GEMM pipeline -------------------------
// DAG: wcvt1 -> g1a -> {g1b || g2a} -> g2b   (g2 kp reads only g_h columns
// written by g1 half kp; disjoint ranges allow overlap)
extern "C" void kernel_launch(void* const* d_in, const int* in_sizes, int n_in,
                              void* d_out, int out_size) {
    const float* x  = (const float*)d_in[0];
    const float* Wg = (const float*)d_in[2];
    const float* W1 = (const float*)d_in[3];
    const float* b1 = (const float*)d_in[4];
    const float* W2 = (const float*)d_in[5];
    const float* b2 = (const float*)d_in[6];
    float* out = (float*)d_out;

    static cudaStream_t s2 = nullptr;
    static cudaEvent_t evStart = nullptr, evAux = nullptr;
    static cudaEvent_t ev1a = nullptr, ev1b = nullptr, evDone = nullptr;
    if (s2 == nullptr) {
        cudaStreamCreateWithFlags(&s2, cudaStreamNonBlocking);
        cudaEventCreateWithFlags(&evStart, cudaEventDisableTiming);
        cudaEventCreateWithFlags(&evAux,   cudaEventDisableTiming);
        cudaEventCreateWithFlags(&ev1a,    cudaEventDisableTiming);
        cudaEventCreateWithFlags(&ev1b,    cudaEventDisableTiming);
        cudaEventCreateWithFlags(&evDone,  cudaEventDisableTiming);
        cudaFuncSetAttribute(ffn_mma<1>, cudaFuncAttributeMaxDynamicSharedMemorySize, SMEM_BYTES);
        cudaFuncSetAttribute(ffn_mma<2>, cudaFuncAttributeMaxDynamicSharedMemorySize, SMEM_BYTES);
    }

    const size_t w4 = (size_t)NE*D*DFF/4;

    // fork
    cudaEventRecord(evStart, 0);
    cudaStreamWaitEvent(s2, evStart, 0);

    // side stream: memset + router/group/half_x + W2 conversion
    cudaMemsetAsync(out, 0, (size_t)OUT_ELEMS * sizeof(float), s2);
    avg_router_kernel<<<BZ, 256, 0, s2>>>(x, Wg, out, out_size);
    group_kernel<<<1, NROWS, 0, s2>>>();
    half_x_kernel<<<(BZ*T*D/4 + 255)/256, 256, 0, s2>>>(x);
    cudaEventRecord(evAux, s2);
    wcvt2_kernel<<<(int)((w4 + 255)/256), 256, 0, s2>>>(W2);

    // main stream: W1 conversion, then gemm1 halves
    wcvt1_kernel<<<(int)((w4 + 255)/256), 256>>>(W1);
    cudaStreamWaitEvent(0, evAux, 0);
    ffn_mma<1><<<dim3(MAX_TILES, (DFF/NT)/2), 512, SMEM_BYTES>>>(b1, b2, out, 0);
    cudaEventRecord(ev1a, 0);
    ffn_mma<1><<<dim3(MAX_TILES, (DFF/NT)/2), 512, SMEM_BYTES>>>(b1, b2, out, 1);
    cudaEventRecord(ev1b, 0);

    // side stream: gemm2 kp0 after g1a (overlaps g1b), kp1 after g1b
    cudaStreamWaitEvent(s2, ev1a, 0);
    ffn_mma<2><<<dim3(MAX_TILES, D/NT), 512, SMEM_BYTES, s2>>>(b1, b2, out, 0);
    cudaStreamWaitEvent(s2, ev1b, 0);
    ffn_mma<2><<<dim3(MAX_TILES, D/NT), 512, SMEM_BYTES, s2>>>(b1, b2, out, 1);
    cudaEventRecord(evDone, s2);

    // join back to origin stream
    cudaStreamWaitEvent(0, evDone, 0);
}

// round 16
// speedup vs baseline: 1.0571x; 1.0571x over previous
#include <cuda_runtime.h>
#include <cuda_fp16.h>
#include <math.h>
#include <stdint.h>

#define BZ   128
#define T    32
#define D    768
#define DFF  3072
#define NE   8
#define NROWS 256
#define OUT_ELEMS (NROWS*T*D)
#define MAX_TILES 72

#define NT        256                 // CTA N tile
#define KC        64                  // K chunk
#define STAGES    4
#define AS_H      72                  // A smem row stride (halves), LDSM-clean
#define BS_H      264                 // B smem k-row stride (halves), LDSM-clean
#define A_STAGE_H (128*AS_H)          // 9216 halves
#define B_STAGE_H (KC*BS_H)           // 16896 halves
#define STAGE_H   (A_STAGE_H + B_STAGE_H)      // 26112 halves
#define SSZ       (STAGE_H*2)                  // stage bytes (52224)
#define SMEM_BYTES (STAGES*SSZ)                // 208896 B

// ---------------- scratch ---------------------------------------------------
__device__ int   g_sel[NROWS];
__device__ int   g_perm[NROWS];
__device__ int   g_tile_e[MAX_TILES];
__device__ int   g_tile_p0[MAX_TILES];
__device__ int   g_tile_rows[MAX_TILES];
__device__ int   g_ntiles;
__device__ __half g_xh[(size_t)BZ*T*D];        // fp16 copy of x
__device__ __half g_h[(size_t)NROWS*T*DFF];    // fp16 intermediate, grouped
__device__ __half g_w1h[(size_t)NE*D*DFF];     // fp16 W1
__device__ __half g_w2h[(size_t)NE*DFF*D];     // fp16 W2

__device__ __forceinline__ float gelu_exact(float v) {
    return 0.5f * v * (1.0f + erff(v * 0.70710678118654752f));
}
__device__ __forceinline__ uint32_t pack_h2(float lo, float hi) {
    uint32_t d;
    asm("cvt.rn.f16x2.f32 %0, %1, %2;" : "=r"(d) : "f"(hi), "f"(lo));
    return d;
}
__device__ __forceinline__ void mma_f16(float* c,
                                        uint32_t a0, uint32_t a1, uint32_t a2, uint32_t a3,
                                        uint32_t b0, uint32_t b1) {
    asm volatile(
        "mma.sync.aligned.m16n8k16.row.col.f32.f16.f16.f32 "
        "{%0,%1,%2,%3}, {%4,%5,%6,%7}, {%8,%9}, {%0,%1,%2,%3};"
        : "+f"(c[0]), "+f"(c[1]), "+f"(c[2]), "+f"(c[3])
        : "r"(a0), "r"(a1), "r"(a2), "r"(a3), "r"(b0), "r"(b1));
}
__device__ __forceinline__ void ldsm4(uint32_t* r, uint32_t addr) {
    asm volatile("ldmatrix.sync.aligned.m8n8.x4.shared.b16 {%0,%1,%2,%3}, [%4];"
        : "=r"(r[0]), "=r"(r[1]), "=r"(r[2]), "=r"(r[3]) : "r"(addr));
}
__device__ __forceinline__ void ldsm4t(uint32_t* r, uint32_t addr) {
    asm volatile("ldmatrix.sync.aligned.m8n8.x4.trans.shared.b16 {%0,%1,%2,%3}, [%4];"
        : "=r"(r[0]), "=r"(r[1]), "=r"(r[2]), "=r"(r[3]) : "r"(addr));
}
__device__ __forceinline__ void cp16(uint32_t saddr, const void* g) {
    asm volatile("cp.async.cg.shared.global [%0], [%1], 16;" :: "r"(saddr), "l"(g));
}

// ---------------- kernel 0a: x -> fp16 --------------------------------------
__global__ void half_x_kernel(const float* __restrict__ x) {
    int i = blockIdx.x * blockDim.x + threadIdx.x;
    const int n4 = BZ*T*D/4;
    if (i < n4) {
        float4 v = ((const float4*)x)[i];
        ((uint2*)g_xh)[i] = make_uint2(pack_h2(v.x, v.y), pack_h2(v.z, v.w));
    }
}

// ---------------- kernel 0b: W1 -> fp16, column half ------------------------
// Converts columns [part*1536, (part+1)*1536) of every (e,d) row.
__global__ void wcvt1_half_kernel(const float* __restrict__ W1, int part) {
    size_t i = (size_t)blockIdx.x * blockDim.x + threadIdx.x;
    const size_t n4 = (size_t)NE*D*(DFF/2)/4;      // uint4 units in this half
    if (i < n4) {
        size_t row = i / (DFF/2/4);                // 0 .. NE*D-1
        size_t cw  = i % (DFF/2/4);                // uint4 index within half
        size_t off = row*DFF + (size_t)part*(DFF/2) + cw*4;
        float4 a = *(const float4*)(W1 + off);
        *(uint2*)(g_w1h + off) = make_uint2(pack_h2(a.x, a.y), pack_h2(a.z, a.w));
    }
}

// ---------------- kernel 0c: W2 -> fp16 -------------------------------------
__global__ void wcvt2_kernel(const float* __restrict__ W2) {
    size_t i = (size_t)blockIdx.x * blockDim.x + threadIdx.x;
    const size_t n4 = (size_t)NE*DFF*D/4;
    if (i < n4) {
        float4 b = ((const float4*)W2)[i];
        ((uint2*)g_w2h)[i] = make_uint2(pack_h2(b.x, b.y), pack_h2(b.z, b.w));
    }
}

// ---------------- kernel 1: fused avg + router ------------------------------
__global__ void avg_router_kernel(const float* __restrict__ x,
                                  const float* __restrict__ Wg,
                                  float* __restrict__ dout, int out_size) {
    __shared__ float xa[D];
    int b = blockIdx.x;
    for (int d = threadIdx.x; d < D; d += blockDim.x) {
        float s = 0.f;
        #pragma unroll
        for (int t = 0; t < T; t++) s += x[((size_t)b*T + t)*D + d];
        xa[d] = s * (1.0f / T);
    }
    __syncthreads();
    if (threadIdx.x < 32) {
        int lane = threadIdx.x;
        int e = lane & 7;
        int chunk = lane >> 3;
        float part = 0.f;
        for (int d = chunk*192; d < (chunk+1)*192; d++) part += xa[d] * Wg[d*NE + e];
        part += __shfl_down_sync(0xffffffffu, part, 16);
        part += __shfl_down_sync(0xffffffffu, part, 8);
        float lv[NE];
        #pragma unroll
        for (int i = 0; i < NE; i++) lv[i] = __shfl_sync(0xffffffffu, part, i);
        if (lane == 0) {
            float mx = lv[0];
            #pragma unroll
            for (int i = 1; i < NE; i++) mx = fmaxf(mx, lv[i]);
            float p[NE]; float sum = 0.f;
            #pragma unroll
            for (int i = 0; i < NE; i++) { p[i] = __expf(lv[i] - mx); sum += p[i]; }
            float inv = 1.0f / sum;
            #pragma unroll
            for (int i = 0; i < NE; i++) p[i] *= inv;
            int i0 = 0;
            #pragma unroll
            for (int i = 1; i < NE; i++) if (p[i] > p[i0]) i0 = i;
            int i1 = (i0 == 0) ? 1 : 0;
            #pragma unroll
            for (int i = 0; i < NE; i++) if (i != i0 && p[i] > p[i1]) i1 = i;
            g_sel[2*b] = i0; g_sel[2*b+1] = i1;
            if (out_size >= OUT_ELEMS + 2*NROWS) {
                dout[OUT_ELEMS + 2*b]             = p[i0];
                dout[OUT_ELEMS + 2*b + 1]         = p[i1];
                dout[OUT_ELEMS + NROWS + 2*b]     = (float)i0;
                dout[OUT_ELEMS + NROWS + 2*b + 1] = (float)i1;
            }
        }
    }
}

// ---------------- kernel 2: group rows by expert ----------------------------
__global__ void group_kernel() {
    __shared__ int ssel[NROWS];
    __shared__ int shist[NE];
    __shared__ int soff[NE];
    int t = threadIdx.x;
    if (t < NE) shist[t] = 0;
    __syncthreads();
    ssel[t] = g_sel[t];
    __syncthreads();
    atomicAdd(&shist[ssel[t]], 1);
    __syncthreads();
    if (t == 0) {
        int pos = 0, tiles = 0;
        for (int e = 0; e < NE; e++) {
            soff[e] = pos;
            int cnt = shist[e];
            for (int r = 0; r < cnt; r += 4) {
                g_tile_e[tiles] = e; g_tile_p0[tiles] = pos + r;
                g_tile_rows[tiles] = min(4, cnt - r); tiles++;
            }
            pos += cnt;
        }
        g_ntiles = tiles;
    }
    __syncthreads();
    int mysel = ssel[t], rank = 0;
    for (int m = 0; m < NROWS; m++)
        if (m < t && ssel[m] == mysel) rank++;
    g_perm[soff[mysel] + rank] = t;
}

// ---------------- fp16 m16n8k16 GEMM, 4-stage, single consume body ----------
// PHASE 1 (part = column half): g_h[:, part*1536 + y*256 ...] = fp16(gelu(...))
// PHASE 2 (kp = blockIdx.z):    out[perm] += g_h @ W2h[e](+b2 on kp0)
// CTA 128x256, 512 threads / 16 warps (2m x 8n), warp tile 64x32.
template<int PHASE>
__global__ __launch_bounds__(512, 1) void ffn_mma(
    const float* __restrict__ b1f, const float* __restrict__ b2f,
    float* __restrict__ out, int part)
{
    const int mt = blockIdx.x;
    if (mt >= g_ntiles) return;
    const int e     = g_tile_e[mt];
    const int p0    = g_tile_p0[mt];
    const int nrows = g_tile_rows[mt];
    const int kp    = (PHASE == 2) ? blockIdx.z : 0;
    const int NF    = (PHASE == 1) ? DFF : D;
    const int kbase = (PHASE == 2) ? kp * (DFF/2) : 0;
    const int NC    = ((PHASE == 1) ? D : DFF/2) / KC;
    const __half* __restrict__ Bsrc = (PHASE == 1) ? (g_w1h + (size_t)e*D*DFF)
                                                   : (g_w2h + (size_t)e*DFF*D);
    const int n0 = (PHASE == 1) ? (part*(DFF/2) + blockIdx.y * NT)
                                : blockIdx.y * NT;
    const int tid = threadIdx.x, wid = tid >> 5, lane = tid & 31;

    extern __shared__ __half smh[];
    uint32_t sbase = (uint32_t)__cvta_generic_to_shared(smh);

    // ---- A loader: 128 rows x 64 halves (8x16B segs), 4 thr/row x 2 segs ----
    const int arow = tid >> 2, aseg = (tid & 3) * 2;
    const __half* aglob;
    {
        int r = ((arow >> 5) < nrows) ? arow : (arow & 31);
        if (PHASE == 1) {
            int n = g_perm[p0 + (r >> 5)];
            aglob = g_xh + ((size_t)(n >> 1)*T + (r & 31)) * (size_t)D;
        } else {
            aglob = g_h + ((size_t)(p0*T + r)) * (size_t)DFF;
        }
    }
    // ---- B loader: 64 k-rows x 256 halves (32x16B segs), 8 thr/row x 4 segs
    const int brow = tid >> 3, bseg = tid & 7;
    const __half* bglob = Bsrc + (size_t)brow*NF + n0;

    const uint32_t aStsB = sbase + (arow*AS_H)*2;
    const uint32_t bStsB = sbase + (A_STAGE_H + brow*BS_H)*2;

    #define ISSUE(k0, soff) do {                                              \
        cp16(aStsB + (soff) + (aseg+0)*16, aglob + (k0) + (aseg+0)*8);        \
        cp16(aStsB + (soff) + (aseg+1)*16, aglob + (k0) + (aseg+1)*8);        \
        _Pragma("unroll")                                                     \
        for (int i = 0; i < 4; i++)                                           \
            cp16(bStsB + (soff) + (bseg + 8*i)*16,                            \
                 bglob + (size_t)(k0)*NF + (bseg + 8*i)*8);                   \
    } while (0)

    // ---- ldmatrix lane bases (stage 0) ----
    const int wm = (wid & 1) * 64;
    const int wn = (wid >> 1) * 32;
    const int lm = lane >> 3;
    const int lr = lane & 7;
    const uint32_t aLdB = sbase + ((wm + (lm & 1)*8 + lr)*AS_H + (lm >> 1)*8)*2;
    const uint32_t bLdB = sbase + (A_STAGE_H + ((lm & 1)*8 + lr)*BS_H
                                   + wn + (lm >> 1)*8)*2;

    float acc[4][4][4];
    #pragma unroll
    for (int i = 0; i < 4; i++)
        #pragma unroll
        for (int j = 0; j < 4; j++)
            #pragma unroll
            for (int q = 0; q < 4; q++) acc[i][j][q] = 0.f;

    // ---- prologue: chunks 0..2 in flight ----
    ISSUE(kbase + 0*KC, 0*SSZ);
    asm volatile("cp.async.commit_group;" ::: "memory");
    ISSUE(kbase + 1*KC, 1*SSZ);
    asm volatile("cp.async.commit_group;" ::: "memory");
    ISSUE(kbase + 2*KC, 2*SSZ);
    asm volatile("cp.async.commit_group;" ::: "memory");

    uint32_t consOff = 0, issOff = 3*SSZ;

    // ---- main loop: single consume body, running stage offsets ----
    for (int c = 0; c < NC; c++) {
        asm volatile("cp.async.wait_group 2;" ::: "memory");  // chunk c landed
        __syncthreads();          // visible to all; consume(c-1) done by all
        if (c + 3 < NC) ISSUE(kbase + (c + 3)*KC, issOff);
        asm volatile("cp.async.commit_group;" ::: "memory");

        const uint32_t aL = aLdB + consOff;
        const uint32_t bL = bLdB + consOff;
        #pragma unroll
        for (int ks = 0; ks < 4; ks++) {
            uint32_t af[4][4], bf[2][4];
            #pragma unroll
            for (int mi = 0; mi < 4; mi++)
                ldsm4(af[mi], aL + (mi*16*AS_H + ks*16)*2);
            #pragma unroll
            for (int nj = 0; nj < 2; nj++)
                ldsm4t(bf[nj], bL + (ks*16*BS_H + nj*16)*2);
            #pragma unroll
            for (int mi = 0; mi < 4; mi++) {
                #pragma unroll
                for (int nj = 0; nj < 2; nj++) {
                    mma_f16(acc[mi][2*nj],   af[mi][0], af[mi][1], af[mi][2],
                            af[mi][3], bf[nj][0], bf[nj][1]);
                    mma_f16(acc[mi][2*nj+1], af[mi][0], af[mi][1], af[mi][2],
                            af[mi][3], bf[nj][2], bf[nj][3]);
                }
            }
        }
        consOff = (consOff == 3*SSZ) ? 0 : consOff + SSZ;
        issOff  = (issOff  == 3*SSZ) ? 0 : issOff  + SSZ;
    }

    // ---- epilogue ----
    const int g = lane >> 2, t4 = lane & 3;
    const float* bias = (PHASE == 1) ? (b1f + e*DFF + n0) : (b2f + e*D + n0);
    #pragma unroll
    for (int mi = 0; mi < 4; mi++) {
        #pragma unroll
        for (int h = 0; h < 2; h++) {
            int r = wm + 16*mi + g + 8*h;
            int br = r >> 5;
            if (br >= nrows) continue;
            if (PHASE == 1) {
                __half* dst = g_h + ((size_t)(p0*T + r)) * (size_t)DFF + n0;
                #pragma unroll
                for (int ni = 0; ni < 4; ni++) {
                    int col = wn + 8*ni + 2*t4;
                    float v0 = gelu_exact(acc[mi][ni][2*h + 0] + bias[col]);
                    float v1 = gelu_exact(acc[mi][ni][2*h + 1] + bias[col + 1]);
                    *(uint32_t*)(dst + col) = pack_h2(v0, v1);
                }
            } else {
                int n = g_perm[p0 + br];
                float* dst = out + ((size_t)n*T + (r & 31)) * (size_t)D + n0;
                #pragma unroll
                for (int ni = 0; ni < 4; ni++) {
                    int col = wn + 8*ni + 2*t4;
                    float v0 = acc[mi][ni][2*h + 0];
                    float v1 = acc[mi][ni][2*h + 1];
                    if (kp == 0) { v0 += bias[col]; v1 += bias[col + 1]; }
                    atomicAdd(dst + col,     v0);   // 2 contributions onto 0:
                    atomicAdd(dst + col + 1, v1);   // order-invariant
                }
            }
        }
    }
    #undef ISSUE
}

// ---------------- launch ------------------------------------------------------
// main:  wcvt1a -> (evAux) g1a -> (evW1b) g1b -> (evMem) g2(z=2)
// side:  router -> group -> half_x [evAux] -> memset -> wcvt2 -> wcvt1b [evW1b,evMem]
extern "C" void kernel_launch(void* const* d_in, const int* in_sizes, int n_in,
                              void* d_out, int out_size) {
    const float* x  = (const float*)d_in[0];
    const float* Wg = (const float*)d_in[2];
    const float* W1 = (const float*)d_in[3];
    const float* b1 = (const float*)d_in[4];
    const float* W2 = (const float*)d_in[5];
    const float* b2 = (const float*)d_in[6];
    float* out = (float*)d_out;

    static cudaStream_t s2 = nullptr;
    static cudaEvent_t evStart = nullptr, evAux = nullptr;
    static cudaEvent_t evW1b = nullptr, evMem = nullptr;
    if (s2 == nullptr) {
        cudaStreamCreateWithFlags(&s2, cudaStreamNonBlocking);
        cudaEventCreateWithFlags(&evStart, cudaEventDisableTiming);
        cudaEventCreateWithFlags(&evAux,   cudaEventDisableTiming);
        cudaEventCreateWithFlags(&evW1b,   cudaEventDisableTiming);
        cudaEventCreateWithFlags(&evMem,   cudaEventDisableTiming);
        cudaFuncSetAttribute(ffn_mma<1>, cudaFuncAttributeMaxDynamicSharedMemorySize, SMEM_BYTES);
        cudaFuncSetAttribute(ffn_mma<2>, cudaFuncAttributeMaxDynamicSharedMemorySize, SMEM_BYTES);
    }

    const size_t w4  = (size_t)NE*DFF*D/4;        // W2 uint4 count
    const size_t wh4 = (size_t)NE*D*(DFF/2)/4;    // W1 half uint4 count

    // fork
    cudaEventRecord(evStart, 0);
    cudaStreamWaitEvent(s2, evStart, 0);

    // side stream: routing aux first (short), then memset + W2 + W1b
    avg_router_kernel<<<BZ, 256, 0, s2>>>(x, Wg, out, out_size);
    group_kernel<<<1, NROWS, 0, s2>>>();
    half_x_kernel<<<(BZ*T*D/4 + 255)/256, 256, 0, s2>>>(x);
    cudaEventRecord(evAux, s2);
    cudaMemsetAsync(out, 0, (size_t)OUT_ELEMS * sizeof(float), s2);
    wcvt2_kernel<<<(int)((w4 + 255)/256), 256, 0, s2>>>(W2);
    wcvt1_half_kernel<<<(int)((wh4 + 255)/256), 256, 0, s2>>>(W1, 1);
    cudaEventRecord(evW1b, s2);
    cudaEventRecord(evMem, s2);

    // main stream: convert W1 first half, then gemm1 halves, then gemm2
    wcvt1_half_kernel<<<(int)((wh4 + 255)/256), 256>>>(W1, 0);
    cudaStreamWaitEvent(0, evAux, 0);
    ffn_mma<1><<<dim3(MAX_TILES, (DFF/NT)/2), 512, SMEM_BYTES>>>(b1, b2, out, 0);
    cudaStreamWaitEvent(0, evW1b, 0);
    ffn_mma<1><<<dim3(MAX_TILES, (DFF/NT)/2), 512, SMEM_BYTES>>>(b1, b2, out, 1);
    cudaStreamWaitEvent(0, evMem, 0);
    ffn_mma<2><<<dim3(MAX_TILES, D/NT, 2), 512, SMEM_BYTES>>>(b1, b2, out, 0);
}

// round 17
// speedup vs baseline: 1.0614x; 1.0040x over previous
#include <cuda_runtime.h>
#include <cuda_fp16.h>
#include <math.h>
#include <stdint.h>

#define BZ   128
#define T    32
#define D    768
#define DFF  3072
#define NE   8
#define NROWS 256
#define OUT_ELEMS (NROWS*T*D)
#define MAX_TILES 72

#define NT        256                 // CTA N tile
#define KC        64                  // K chunk
#define STAGES    4
#define AS_H      72                  // A smem row stride (halves), LDSM-clean
#define BS_H      264                 // B smem k-row stride (halves), LDSM-clean
#define A_STAGE_H (128*AS_H)          // 9216 halves
#define B_STAGE_H (KC*BS_H)           // 16896 halves
#define STAGE_H   (A_STAGE_H + B_STAGE_H)      // 26112 halves
#define SSZ       (STAGE_H*2)                  // stage bytes (52224)
#define SMEM_BYTES (STAGES*SSZ)                // 208896 B

// ---------------- scratch ---------------------------------------------------
__device__ int   g_sel[NROWS];
__device__ int   g_perm[NROWS];
__device__ int   g_tile_e[MAX_TILES];
__device__ int   g_tile_p0[MAX_TILES];
__device__ int   g_tile_rows[MAX_TILES];
__device__ int   g_ntiles;
__device__ __half g_xh[(size_t)BZ*T*D];        // fp16 copy of x
__device__ __half g_h[(size_t)NROWS*T*DFF];    // fp16 intermediate, grouped
__device__ __half g_w1h[(size_t)NE*D*DFF];     // fp16 W1
__device__ __half g_w2h[(size_t)NE*DFF*D];     // fp16 W2

__device__ __forceinline__ float gelu_exact(float v) {
    return 0.5f * v * (1.0f + erff(v * 0.70710678118654752f));
}
__device__ __forceinline__ uint32_t pack_h2(float lo, float hi) {
    uint32_t d;
    asm("cvt.rn.f16x2.f32 %0, %1, %2;" : "=r"(d) : "f"(hi), "f"(lo));
    return d;
}
__device__ __forceinline__ void mma_f16(float* c,
                                        uint32_t a0, uint32_t a1, uint32_t a2, uint32_t a3,
                                        uint32_t b0, uint32_t b1) {
    asm volatile(
        "mma.sync.aligned.m16n8k16.row.col.f32.f16.f16.f32 "
        "{%0,%1,%2,%3}, {%4,%5,%6,%7}, {%8,%9}, {%0,%1,%2,%3};"
        : "+f"(c[0]), "+f"(c[1]), "+f"(c[2]), "+f"(c[3])
        : "r"(a0), "r"(a1), "r"(a2), "r"(a3), "r"(b0), "r"(b1));
}
__device__ __forceinline__ void ldsm4(uint32_t* r, uint32_t addr) {
    asm volatile("ldmatrix.sync.aligned.m8n8.x4.shared.b16 {%0,%1,%2,%3}, [%4];"
        : "=r"(r[0]), "=r"(r[1]), "=r"(r[2]), "=r"(r[3]) : "r"(addr));
}
__device__ __forceinline__ void ldsm4t(uint32_t* r, uint32_t addr) {
    asm volatile("ldmatrix.sync.aligned.m8n8.x4.trans.shared.b16 {%0,%1,%2,%3}, [%4];"
        : "=r"(r[0]), "=r"(r[1]), "=r"(r[2]), "=r"(r[3]) : "r"(addr));
}
__device__ __forceinline__ void cp16(uint32_t saddr, const void* g) {
    asm volatile("cp.async.cg.shared.global [%0], [%1], 16;" :: "r"(saddr), "l"(g));
}

// ---------------- kernel 0b: W1 -> fp16, column half ------------------------
__global__ void wcvt1_half_kernel(const float* __restrict__ W1, int part) {
    size_t i = (size_t)blockIdx.x * blockDim.x + threadIdx.x;
    const size_t n4 = (size_t)NE*D*(DFF/2)/4;
    if (i < n4) {
        size_t row = i / (DFF/2/4);
        size_t cw  = i % (DFF/2/4);
        size_t off = row*DFF + (size_t)part*(DFF/2) + cw*4;
        float4 a = *(const float4*)(W1 + off);
        *(uint2*)(g_w1h + off) = make_uint2(pack_h2(a.x, a.y), pack_h2(a.z, a.w));
    }
}

// ---------------- kernel 0c: W2 -> fp16 -------------------------------------
__global__ void wcvt2_kernel(const float* __restrict__ W2) {
    size_t i = (size_t)blockIdx.x * blockDim.x + threadIdx.x;
    const size_t n4 = (size_t)NE*DFF*D/4;
    if (i < n4) {
        float4 b = ((const float4*)W2)[i];
        ((uint2*)g_w2h)[i] = make_uint2(pack_h2(b.x, b.y), pack_h2(b.z, b.w));
    }
}

// ---------------- kernel 1: fused avg + router + half_x ---------------------
// Block b: converts x slice [b*6144, (b+1)*6144) uint4 to fp16 AND computes
// router decisions for batch row b.
__global__ void avg_router_kernel(const float* __restrict__ x,
                                  const float* __restrict__ Wg,
                                  float* __restrict__ dout, int out_size) {
    __shared__ float xa[D];
    int b = blockIdx.x;

    // fp16 conversion slice (independent work, overlaps avg loads)
    {
        const int per_blk = (BZ*T*D/4) / BZ;    // 6144 uint4 per block
        int base = b * per_blk;
        for (int i = threadIdx.x; i < per_blk; i += blockDim.x) {
            float4 v = ((const float4*)x)[base + i];
            ((uint2*)g_xh)[base + i] =
                make_uint2(pack_h2(v.x, v.y), pack_h2(v.z, v.w));
        }
    }

    for (int d = threadIdx.x; d < D; d += blockDim.x) {
        float s = 0.f;
        #pragma unroll
        for (int t = 0; t < T; t++) s += x[((size_t)b*T + t)*D + d];
        xa[d] = s * (1.0f / T);
    }
    __syncthreads();
    if (threadIdx.x < 32) {
        int lane = threadIdx.x;
        int e = lane & 7;
        int chunk = lane >> 3;
        float part = 0.f;
        for (int d = chunk*192; d < (chunk+1)*192; d++) part += xa[d] * Wg[d*NE + e];
        part += __shfl_down_sync(0xffffffffu, part, 16);
        part += __shfl_down_sync(0xffffffffu, part, 8);
        float lv[NE];
        #pragma unroll
        for (int i = 0; i < NE; i++) lv[i] = __shfl_sync(0xffffffffu, part, i);
        if (lane == 0) {
            float mx = lv[0];
            #pragma unroll
            for (int i = 1; i < NE; i++) mx = fmaxf(mx, lv[i]);
            float p[NE]; float sum = 0.f;
            #pragma unroll
            for (int i = 0; i < NE; i++) { p[i] = __expf(lv[i] - mx); sum += p[i]; }
            float inv = 1.0f / sum;
            #pragma unroll
            for (int i = 0; i < NE; i++) p[i] *= inv;
            int i0 = 0;
            #pragma unroll
            for (int i = 1; i < NE; i++) if (p[i] > p[i0]) i0 = i;
            int i1 = (i0 == 0) ? 1 : 0;
            #pragma unroll
            for (int i = 0; i < NE; i++) if (i != i0 && p[i] > p[i1]) i1 = i;
            g_sel[2*b] = i0; g_sel[2*b+1] = i1;
            if (out_size >= OUT_ELEMS + 2*NROWS) {
                dout[OUT_ELEMS + 2*b]             = p[i0];
                dout[OUT_ELEMS + 2*b + 1]         = p[i1];
                dout[OUT_ELEMS + NROWS + 2*b]     = (float)i0;
                dout[OUT_ELEMS + NROWS + 2*b + 1] = (float)i1;
            }
        }
    }
}

// ---------------- kernel 2: group rows by expert (ballot ranking) -----------
__global__ void group_kernel() {
    __shared__ int wcnt[8][NE];     // per-warp expert counts
    __shared__ int soff[NE];
    int t = threadIdx.x, w = t >> 5, lane = t & 31;
    if (t < 64) ((int*)wcnt)[t] = 0;
    __syncthreads();

    int mysel = g_sel[t];
    unsigned m = __match_any_sync(0xffffffffu, mysel);
    int rank_in_warp = __popc(m & ((1u << lane) - 1u));
    int leader = __ffs(m) - 1;
    if (lane == leader) wcnt[w][mysel] = __popc(m);
    __syncthreads();

    if (t == 0) {
        int pos = 0, tiles = 0;
        for (int e = 0; e < NE; e++) {
            soff[e] = pos;
            int cnt = 0;
            #pragma unroll
            for (int ww = 0; ww < 8; ww++) cnt += wcnt[ww][e];
            for (int r = 0; r < cnt; r += 4) {
                g_tile_e[tiles] = e; g_tile_p0[tiles] = pos + r;
                g_tile_rows[tiles] = min(4, cnt - r); tiles++;
            }
            pos += cnt;
        }
        g_ntiles = tiles;
    }
    __syncthreads();

    int rank = rank_in_warp;
    #pragma unroll
    for (int ww = 0; ww < 8; ww++)
        if (ww < w) rank += wcnt[ww][mysel];
    g_perm[soff[mysel] + rank] = t;
}

// ---------------- fp16 m16n8k16 GEMM, 4-stage, single consume body ----------
// PHASE 1 (part = column half): g_h[:, part*1536 + y*256 ...] = fp16(gelu(...))
// PHASE 2 (kp = blockIdx.z):    out[perm] += g_h @ W2h[e](+b2 on kp0)
// CTA 128x256, 512 threads / 16 warps (2m x 8n), warp tile 64x32.
template<int PHASE>
__global__ __launch_bounds__(512, 1) void ffn_mma(
    const float* __restrict__ b1f, const float* __restrict__ b2f,
    float* __restrict__ out, int part)
{
    const int mt = blockIdx.x;
    if (mt >= g_ntiles) return;
    const int e     = g_tile_e[mt];
    const int p0    = g_tile_p0[mt];
    const int nrows = g_tile_rows[mt];
    const int kp    = (PHASE == 2) ? blockIdx.z : 0;
    const int NF    = (PHASE == 1) ? DFF : D;
    const int kbase = (PHASE == 2) ? kp * (DFF/2) : 0;
    const int NC    = ((PHASE == 1) ? D : DFF/2) / KC;
    const __half* __restrict__ Bsrc = (PHASE == 1) ? (g_w1h + (size_t)e*D*DFF)
                                                   : (g_w2h + (size_t)e*DFF*D);
    const int n0 = (PHASE == 1) ? (part*(DFF/2) + blockIdx.y * NT)
                                : blockIdx.y * NT;
    const int tid = threadIdx.x, wid = tid >> 5, lane = tid & 31;

    extern __shared__ __half smh[];
    uint32_t sbase = (uint32_t)__cvta_generic_to_shared(smh);

    const int arow = tid >> 2, aseg = (tid & 3) * 2;
    const __half* aglob;
    {
        int r = ((arow >> 5) < nrows) ? arow : (arow & 31);
        if (PHASE == 1) {
            int n = g_perm[p0 + (r >> 5)];
            aglob = g_xh + ((size_t)(n >> 1)*T + (r & 31)) * (size_t)D;
        } else {
            aglob = g_h + ((size_t)(p0*T + r)) * (size_t)DFF;
        }
    }
    const int brow = tid >> 3, bseg = tid & 7;
    const __half* bglob = Bsrc + (size_t)brow*NF + n0;

    const uint32_t aStsB = sbase + (arow*AS_H)*2;
    const uint32_t bStsB = sbase + (A_STAGE_H + brow*BS_H)*2;

    #define ISSUE(k0, soff) do {                                              \
        cp16(aStsB + (soff) + (aseg+0)*16, aglob + (k0) + (aseg+0)*8);        \
        cp16(aStsB + (soff) + (aseg+1)*16, aglob + (k0) + (aseg+1)*8);        \
        _Pragma("unroll")                                                     \
        for (int i = 0; i < 4; i++)                                           \
            cp16(bStsB + (soff) + (bseg + 8*i)*16,                            \
                 bglob + (size_t)(k0)*NF + (bseg + 8*i)*8);                   \
    } while (0)

    const int wm = (wid & 1) * 64;
    const int wn = (wid >> 1) * 32;
    const int lm = lane >> 3;
    const int lr = lane & 7;
    const uint32_t aLdB = sbase + ((wm + (lm & 1)*8 + lr)*AS_H + (lm >> 1)*8)*2;
    const uint32_t bLdB = sbase + (A_STAGE_H + ((lm & 1)*8 + lr)*BS_H
                                   + wn + (lm >> 1)*8)*2;

    float acc[4][4][4];
    #pragma unroll
    for (int i = 0; i < 4; i++)
        #pragma unroll
        for (int j = 0; j < 4; j++)
            #pragma unroll
            for (int q = 0; q < 4; q++) acc[i][j][q] = 0.f;

    ISSUE(kbase + 0*KC, 0*SSZ);
    asm volatile("cp.async.commit_group;" ::: "memory");
    ISSUE(kbase + 1*KC, 1*SSZ);
    asm volatile("cp.async.commit_group;" ::: "memory");
    ISSUE(kbase + 2*KC, 2*SSZ);
    asm volatile("cp.async.commit_group;" ::: "memory");

    uint32_t consOff = 0, issOff = 3*SSZ;

    for (int c = 0; c < NC; c++) {
        asm volatile("cp.async.wait_group 2;" ::: "memory");
        __syncthreads();
        if (c + 3 < NC) ISSUE(kbase + (c + 3)*KC, issOff);
        asm volatile("cp.async.commit_group;" ::: "memory");

        const uint32_t aL = aLdB + consOff;
        const uint32_t bL = bLdB + consOff;
        #pragma unroll
        for (int ks = 0; ks < 4; ks++) {
            uint32_t af[4][4], bf[2][4];
            #pragma unroll
            for (int mi = 0; mi < 4; mi++)
                ldsm4(af[mi], aL + (mi*16*AS_H + ks*16)*2);
            #pragma unroll
            for (int nj = 0; nj < 2; nj++)
                ldsm4t(bf[nj], bL + (ks*16*BS_H + nj*16)*2);
            #pragma unroll
            for (int mi = 0; mi < 4; mi++) {
                #pragma unroll
                for (int nj = 0; nj < 2; nj++) {
                    mma_f16(acc[mi][2*nj],   af[mi][0], af[mi][1], af[mi][2],
                            af[mi][3], bf[nj][0], bf[nj][1]);
                    mma_f16(acc[mi][2*nj+1], af[mi][0], af[mi][1], af[mi][2],
                            af[mi][3], bf[nj][2], bf[nj][3]);
                }
            }
        }
        consOff = (consOff == 3*SSZ) ? 0 : consOff + SSZ;
        issOff  = (issOff  == 3*SSZ) ? 0 : issOff  + SSZ;
    }

    const int g = lane >> 2, t4 = lane & 3;
    const float* bias = (PHASE == 1) ? (b1f + e*DFF + n0) : (b2f + e*D + n0);
    #pragma unroll
    for (int mi = 0; mi < 4; mi++) {
        #pragma unroll
        for (int h = 0; h < 2; h++) {
            int r = wm + 16*mi + g + 8*h;
            int br = r >> 5;
            if (br >= nrows) continue;
            if (PHASE == 1) {
                __half* dst = g_h + ((size_t)(p0*T + r)) * (size_t)DFF + n0;
                #pragma unroll
                for (int ni = 0; ni < 4; ni++) {
                    int col = wn + 8*ni + 2*t4;
                    float v0 = gelu_exact(acc[mi][ni][2*h + 0] + bias[col]);
                    float v1 = gelu_exact(acc[mi][ni][2*h + 1] + bias[col + 1]);
                    *(uint32_t*)(dst + col) = pack_h2(v0, v1);
                }
            } else {
                int n = g_perm[p0 + br];
                float* dst = out + ((size_t)n*T + (r & 31)) * (size_t)D + n0;
                #pragma unroll
                for (int ni = 0; ni < 4; ni++) {
                    int col = wn + 8*ni + 2*t4;
                    float v0 = acc[mi][ni][2*h + 0];
                    float v1 = acc[mi][ni][2*h + 1];
                    if (kp == 0) { v0 += bias[col]; v1 += bias[col + 1]; }
                    atomicAdd(dst + col,     v0);   // 2 contributions onto 0:
                    atomicAdd(dst + col + 1, v1);   // order-invariant
                }
            }
        }
    }
    #undef ISSUE
}

// ---------------- launch ------------------------------------------------------
// main:  wcvt1a -> (evAux) g1a -> (evW1b) g1b -> (evMem) g2(z=2)
// side:  avg_router+half_x -> group [evAux] -> memset -> wcvt2 -> wcvt1b [evW1b/evMem]
extern "C" void kernel_launch(void* const* d_in, const int* in_sizes, int n_in,
                              void* d_out, int out_size) {
    const float* x  = (const float*)d_in[0];
    const float* Wg = (const float*)d_in[2];
    const float* W1 = (const float*)d_in[3];
    const float* b1 = (const float*)d_in[4];
    const float* W2 = (const float*)d_in[5];
    const float* b2 = (const float*)d_in[6];
    float* out = (float*)d_out;

    static cudaStream_t s2 = nullptr;
    static cudaEvent_t evStart = nullptr, evAux = nullptr;
    static cudaEvent_t evW1b = nullptr, evMem = nullptr;
    if (s2 == nullptr) {
        cudaStreamCreateWithFlags(&s2, cudaStreamNonBlocking);
        cudaEventCreateWithFlags(&evStart, cudaEventDisableTiming);
        cudaEventCreateWithFlags(&evAux,   cudaEventDisableTiming);
        cudaEventCreateWithFlags(&evW1b,   cudaEventDisableTiming);
        cudaEventCreateWithFlags(&evMem,   cudaEventDisableTiming);
        cudaFuncSetAttribute(ffn_mma<1>, cudaFuncAttributeMaxDynamicSharedMemorySize, SMEM_BYTES);
        cudaFuncSetAttribute(ffn_mma<2>, cudaFuncAttributeMaxDynamicSharedMemorySize, SMEM_BYTES);
    }

    const size_t w4  = (size_t)NE*DFF*D/4;
    const size_t wh4 = (size_t)NE*D*(DFF/2)/4;

    cudaEventRecord(evStart, 0);
    cudaStreamWaitEvent(s2, evStart, 0);

    // side stream: fused router+half_x, ballot group, then memset + W2 + W1b
    avg_router_kernel<<<BZ, 256, 0, s2>>>(x, Wg, out, out_size);
    group_kernel<<<1, NROWS, 0, s2>>>();
    cudaEventRecord(evAux, s2);
    cudaMemsetAsync(out, 0, (size_t)OUT_ELEMS * sizeof(float), s2);
    wcvt2_kernel<<<(int)((w4 + 255)/256), 256, 0, s2>>>(W2);
    wcvt1_half_kernel<<<(int)((wh4 + 255)/256), 256, 0, s2>>>(W1, 1);
    cudaEventRecord(evW1b, s2);
    cudaEventRecord(evMem, s2);

    // main stream: convert W1 first half, then gemm1 halves, then gemm2
    wcvt1_half_kernel<<<(int)((wh4 + 255)/256), 256>>>(W1, 0);
    cudaStreamWaitEvent(0, evAux, 0);
    ffn_mma<1><<<dim3(MAX_TILES, (DFF/NT)/2), 512, SMEM_BYTES>>>(b1, b2, out, 0);
    cudaStreamWaitEvent(0, evW1b, 0);
    ffn_mma<1><<<dim3(MAX_TILES, (DFF/NT)/2), 512, SMEM_BYTES>>>(b1, b2, out, 1);
    cudaStreamWaitEvent(0, evMem, 0);
    ffn_mma<2><<<dim3(MAX_TILES, D/NT, 2), 512, SMEM_BYTES>>>(b1, b2, out, 0);
}